// round 2
// baseline (speedup 1.0000x reference)
#include <cuda_runtime.h>
#include <math.h>

#define BB 4
#define TT 2048
#define EE 1024
#define DD 128

// ---------------- scratch (no allocations allowed) ----------------
__device__ float g_Q[BB * TT * DD];
__device__ float g_K[BB * TT * DD];
__device__ float g_V[BB * TT * DD];
__device__ float2 g_rope[TT * (DD / 2)];

// ---------------- RoPE cos/sin table (double precision) ----------------
__global__ void rope_table_kernel() {
    int t = blockIdx.x;          // 0..2047
    int i = threadIdx.x;         // 0..63
    double freq = exp(-log(10000.0) * (double)(2 * i) / (double)DD);
    double ang = (double)t * freq;
    g_rope[t * (DD / 2) + i] = make_float2((float)cos(ang), (float)sin(ang));
}

// ---------------- QKV projection: X[8192,1024] @ W[d,1024]^T ----------------
// BM=64, BN=64, BK=16, 256 threads, 4x4 register tile. RoPE fused for Q,K.
__global__ __launch_bounds__(256) void proj_kernel(
    const float* __restrict__ X,
    const float* __restrict__ Wq,
    const float* __restrict__ Wk,
    const float* __restrict__ Wv)
{
    const float* W;
    float* Out;
    int do_rope;
    float scale;
    int z = blockIdx.z;
    if (z == 0)      { W = Wq; Out = g_Q; do_rope = 1; scale = 0.08838834764831845f; } // 1/sqrt(128)
    else if (z == 1) { W = Wk; Out = g_K; do_rope = 1; scale = 1.0f; }
    else             { W = Wv; Out = g_V; do_rope = 0; scale = 1.0f; }

    __shared__ float sA[16][68];   // [k][m]
    __shared__ float sB[16][68];   // [k][n]

    int tid = threadIdx.x;
    int tx = tid & 15;
    int ty = tid >> 4;
    int mb = blockIdx.x * 64;      // global row base (b*T + t)
    int nb = blockIdx.y * 64;      // output col base

    int lrow = tid >> 2;           // 0..63
    int lk4  = (tid & 3) * 4;      // 0,4,8,12

    float acc[4][4] = {};

    for (int k0 = 0; k0 < EE; k0 += 16) {
        float4 a = *(const float4*)&X[(size_t)(mb + lrow) * EE + k0 + lk4];
        float4 b = *(const float4*)&W[(size_t)(nb + lrow) * EE + k0 + lk4];
        __syncthreads();
        sA[lk4 + 0][lrow] = a.x; sA[lk4 + 1][lrow] = a.y;
        sA[lk4 + 2][lrow] = a.z; sA[lk4 + 3][lrow] = a.w;
        sB[lk4 + 0][lrow] = b.x; sB[lk4 + 1][lrow] = b.y;
        sB[lk4 + 2][lrow] = b.z; sB[lk4 + 3][lrow] = b.w;
        __syncthreads();
        #pragma unroll
        for (int kk = 0; kk < 16; kk++) {
            float ra[4], rb[4];
            #pragma unroll
            for (int i = 0; i < 4; i++) ra[i] = sA[kk][ty * 4 + i];
            #pragma unroll
            for (int j = 0; j < 4; j++) rb[j] = sB[kk][tx * 4 + j];
            #pragma unroll
            for (int i = 0; i < 4; i++)
                #pragma unroll
                for (int j = 0; j < 4; j++)
                    acc[i][j] += ra[i] * rb[j];
        }
    }

    int c0 = nb + tx * 4;
    #pragma unroll
    for (int i = 0; i < 4; i++) {
        int row = mb + ty * 4 + i;
        if (do_rope) {
            int t = row & (TT - 1);
            #pragma unroll
            for (int jp = 0; jp < 2; jp++) {
                float2 cs = g_rope[t * (DD / 2) + (c0 >> 1) + jp];
                float a = acc[i][2 * jp], b = acc[i][2 * jp + 1];
                acc[i][2 * jp]     = (a * cs.x - b * cs.y) * scale;
                acc[i][2 * jp + 1] = (a * cs.y + b * cs.x) * scale;
            }
        }
        float4 o = make_float4(acc[i][0], acc[i][1], acc[i][2], acc[i][3]);
        *(float4*)&Out[(size_t)row * DD + c0] = o;
    }
}

// ---------------- flash attention (fp32) ----------------
// One CTA per (batch, 64-query tile). 256 threads: tx=tid&15, ty=tid>>4.
// S cols per thread: tx+16j (j<4). O cols per thread: tx+16jj (jj<8).
#define SQS 129   // row stride for Q/K/V tiles (conflict-free for tx-strided reads)
#define SPS 65    // row stride for P tile

#define ATTN_SMEM ((2 * 64 * SQS + 64 * SPS) * 4)

__global__ __launch_bounds__(256) void attn_kernel(float* __restrict__ Out) {
    extern __shared__ float sm[];
    float* sQ  = sm;                    // 64 x SQS
    float* sKV = sm + 64 * SQS;         // 64 x SQS (K then V, reused)
    float* sP  = sKV + 64 * SQS;        // 64 x SPS

    int b  = blockIdx.y;
    int qt = blockIdx.x;                // 0..31
    int q0 = qt * 64;
    int tid = threadIdx.x;
    int tx = tid & 15;
    int ty = tid >> 4;
    int r0 = ty * 4;

    // load Q tile
    const float* Qg = g_Q + ((size_t)b * TT + q0) * DD;
    for (int idx = tid; idx < 64 * 32; idx += 256) {
        int r = idx >> 5, c4 = idx & 31;
        float4 v = *(const float4*)&Qg[r * DD + c4 * 4];
        float* dst = &sQ[r * SQS + c4 * 4];
        dst[0] = v.x; dst[1] = v.y; dst[2] = v.z; dst[3] = v.w;
    }

    float O[4][8];
    #pragma unroll
    for (int i = 0; i < 4; i++)
        #pragma unroll
        for (int j = 0; j < 8; j++) O[i][j] = 0.0f;
    float m_i[4], l_i[4];
    #pragma unroll
    for (int i = 0; i < 4; i++) { m_i[i] = -1e30f; l_i[i] = 0.0f; }

    for (int kt = 0; kt <= qt; kt++) {
        __syncthreads();   // prev PV done with sKV / sP (also covers Q-load on iter 0)
        const float* Kg = g_K + ((size_t)b * TT + kt * 64) * DD;
        for (int idx = tid; idx < 64 * 32; idx += 256) {
            int r = idx >> 5, c4 = idx & 31;
            float4 v = *(const float4*)&Kg[r * DD + c4 * 4];
            float* dst = &sKV[r * SQS + c4 * 4];
            dst[0] = v.x; dst[1] = v.y; dst[2] = v.z; dst[3] = v.w;
        }
        __syncthreads();

        // S = Q K^T  (rows r0..r0+3, cols tx+16j)
        float acc[4][4] = {};
        #pragma unroll 4
        for (int d = 0; d < DD; d++) {
            float rq[4], rk[4];
            #pragma unroll
            for (int i = 0; i < 4; i++) rq[i] = sQ[(r0 + i) * SQS + d];
            #pragma unroll
            for (int j = 0; j < 4; j++) rk[j] = sKV[(tx + 16 * j) * SQS + d];
            #pragma unroll
            for (int i = 0; i < 4; i++)
                #pragma unroll
                for (int j = 0; j < 4; j++)
                    acc[i][j] += rq[i] * rk[j];
        }

        if (kt == qt) {  // causal mask on diagonal tile
            #pragma unroll
            for (int i = 0; i < 4; i++)
                #pragma unroll
                for (int j = 0; j < 4; j++)
                    if (tx + 16 * j > r0 + i) acc[i][j] = -1e30f;
        }

        // online softmax update
        #pragma unroll
        for (int i = 0; i < 4; i++) {
            float tmax = fmaxf(fmaxf(acc[i][0], acc[i][1]), fmaxf(acc[i][2], acc[i][3]));
            #pragma unroll
            for (int s = 8; s >= 1; s >>= 1)
                tmax = fmaxf(tmax, __shfl_xor_sync(0xffffffffu, tmax, s));
            float mnew = fmaxf(m_i[i], tmax);
            float corr = __expf(m_i[i] - mnew);
            float psum = 0.0f;
            #pragma unroll
            for (int j = 0; j < 4; j++) {
                acc[i][j] = __expf(acc[i][j] - mnew);
                psum += acc[i][j];
            }
            #pragma unroll
            for (int s = 8; s >= 1; s >>= 1)
                psum += __shfl_xor_sync(0xffffffffu, psum, s);
            l_i[i] = l_i[i] * corr + psum;
            m_i[i] = mnew;
            #pragma unroll
            for (int jj = 0; jj < 8; jj++) O[i][jj] *= corr;
            #pragma unroll
            for (int j = 0; j < 4; j++)
                sP[(r0 + i) * SPS + tx + 16 * j] = acc[i][j];
        }
        __syncthreads();   // S phase done: safe to overwrite sKV with V

        const float* Vg = g_V + ((size_t)b * TT + kt * 64) * DD;
        for (int idx = tid; idx < 64 * 32; idx += 256) {
            int r = idx >> 5, c4 = idx & 31;
            float4 v = *(const float4*)&Vg[r * DD + c4 * 4];
            float* dst = &sKV[r * SQS + c4 * 4];
            dst[0] = v.x; dst[1] = v.y; dst[2] = v.z; dst[3] = v.w;
        }
        __syncthreads();

        // O += P @ V
        #pragma unroll 2
        for (int kk = 0; kk < 64; kk++) {
            float rp[4], rv[8];
            #pragma unroll
            for (int i = 0; i < 4; i++) rp[i] = sP[(r0 + i) * SPS + kk];
            #pragma unroll
            for (int jj = 0; jj < 8; jj++) rv[jj] = sKV[kk * SQS + tx + 16 * jj];
            #pragma unroll
            for (int i = 0; i < 4; i++)
                #pragma unroll
                for (int jj = 0; jj < 8; jj++)
                    O[i][jj] += rp[i] * rv[jj];
        }
    }

    // epilogue: normalize and store
    float* Og = Out + ((size_t)b * TT + q0) * DD;
    #pragma unroll
    for (int i = 0; i < 4; i++) {
        float inv = 1.0f / l_i[i];
        #pragma unroll
        for (int jj = 0; jj < 8; jj++)
            Og[(r0 + i) * DD + tx + 16 * jj] = O[i][jj] * inv;
    }
}

// ---------------- launch ----------------
extern "C" void kernel_launch(void* const* d_in, const int* in_sizes, int n_in,
                              void* d_out, int out_size) {
    (void)in_sizes; (void)n_in; (void)out_size;
    const float* X  = (const float*)d_in[0];
    const float* Wq = (const float*)d_in[1];
    const float* Wk = (const float*)d_in[2];
    const float* Wv = (const float*)d_in[3];
    float* Out = (float*)d_out;

    rope_table_kernel<<<TT, DD / 2>>>();

    dim3 pg(BB * TT / 64, DD / 64, 3);
    proj_kernel<<<pg, 256>>>(X, Wq, Wk, Wv);

    cudaFuncSetAttribute(attn_kernel, cudaFuncAttributeMaxDynamicSharedMemorySize, ATTN_SMEM);
    dim3 ag(TT / 64, BB);
    attn_kernel<<<ag, 256, ATTN_SMEM>>>(Out);
}

// round 3
// speedup vs baseline: 1.1849x; 1.1849x over previous
#include <cuda_runtime.h>
#include <math.h>

#define BB 4
#define TT 2048
#define EE 1024
#define DD 128

// ---------------- scratch (no allocations allowed) ----------------
__device__ float g_Q[BB * TT * DD];
__device__ float g_K[BB * TT * DD];
__device__ float g_V[BB * TT * DD];
__device__ float2 g_rope[TT * (DD / 2)];
// split-K partials: [split][b][t][d], unnormalized O plus per-row m,l
__device__ float g_Opart[2 * BB * TT * DD];
__device__ float g_Mpart[2 * BB * TT];
__device__ float g_Lpart[2 * BB * TT];

// ---------------- RoPE cos/sin table (double precision) ----------------
__global__ void rope_table_kernel() {
    int t = blockIdx.x;          // 0..2047
    int i = threadIdx.x;         // 0..63
    double freq = exp(-log(10000.0) * (double)(2 * i) / (double)DD);
    double ang = (double)t * freq;
    g_rope[t * (DD / 2) + i] = make_float2((float)cos(ang), (float)sin(ang));
}

// ---------------- QKV projection: X[8192,1024] @ W[d,1024]^T ----------------
// BM=64, BN=64, BK=16, 256 threads, 4x4 register tile. RoPE fused for Q,K.
// Global loads for tile k+1 are issued BEFORE the compute of tile k (latency hidden).
__global__ __launch_bounds__(256) void proj_kernel(
    const float* __restrict__ X,
    const float* __restrict__ Wq,
    const float* __restrict__ Wk,
    const float* __restrict__ Wv)
{
    const float* W;
    float* Out;
    int do_rope;
    float scale;
    int z = blockIdx.z;
    if (z == 0)      { W = Wq; Out = g_Q; do_rope = 1; scale = 0.08838834764831845f; } // 1/sqrt(128)
    else if (z == 1) { W = Wk; Out = g_K; do_rope = 1; scale = 1.0f; }
    else             { W = Wv; Out = g_V; do_rope = 0; scale = 1.0f; }

    __shared__ float sA[16][68];   // [k][m]
    __shared__ float sB[16][68];   // [k][n]

    int tid = threadIdx.x;
    int tx = tid & 15;
    int ty = tid >> 4;
    int mb = blockIdx.x * 64;      // global row base (b*T + t)
    int nb = blockIdx.y * 64;      // output col base

    int lrow = tid >> 2;           // 0..63
    int lk4  = (tid & 3) * 4;      // 0,4,8,12

    const float* Arow = &X[(size_t)(mb + lrow) * EE + lk4];
    const float* Brow = &W[(size_t)(nb + lrow) * EE + lk4];

    float acc[4][4] = {};

    // prefetch first slab
    float4 a = *(const float4*)&Arow[0];
    float4 b = *(const float4*)&Brow[0];

    for (int k0 = 0; k0 < EE; k0 += 16) {
        __syncthreads();
        sA[lk4 + 0][lrow] = a.x; sA[lk4 + 1][lrow] = a.y;
        sA[lk4 + 2][lrow] = a.z; sA[lk4 + 3][lrow] = a.w;
        sB[lk4 + 0][lrow] = b.x; sB[lk4 + 1][lrow] = b.y;
        sB[lk4 + 2][lrow] = b.z; sB[lk4 + 3][lrow] = b.w;
        __syncthreads();
        if (k0 + 16 < EE) {        // prefetch next slab; overlaps compute below
            a = *(const float4*)&Arow[k0 + 16];
            b = *(const float4*)&Brow[k0 + 16];
        }
        #pragma unroll
        for (int kk = 0; kk < 16; kk++) {
            float ra[4], rb[4];
            #pragma unroll
            for (int i = 0; i < 4; i++) ra[i] = sA[kk][ty * 4 + i];
            #pragma unroll
            for (int j = 0; j < 4; j++) rb[j] = sB[kk][tx * 4 + j];
            #pragma unroll
            for (int i = 0; i < 4; i++)
                #pragma unroll
                for (int j = 0; j < 4; j++)
                    acc[i][j] += ra[i] * rb[j];
        }
    }

    int c0 = nb + tx * 4;
    #pragma unroll
    for (int i = 0; i < 4; i++) {
        int row = mb + ty * 4 + i;
        if (do_rope) {
            int t = row & (TT - 1);
            #pragma unroll
            for (int jp = 0; jp < 2; jp++) {
                float2 cs = g_rope[t * (DD / 2) + (c0 >> 1) + jp];
                float va = acc[i][2 * jp], vb = acc[i][2 * jp + 1];
                acc[i][2 * jp]     = (va * cs.x - vb * cs.y) * scale;
                acc[i][2 * jp + 1] = (va * cs.y + vb * cs.x) * scale;
            }
        }
        float4 o = make_float4(acc[i][0], acc[i][1], acc[i][2], acc[i][3]);
        *(float4*)&Out[(size_t)row * DD + c0] = o;
    }
}

// ---------------- split-K flash attention (fp32) ----------------
// Grid (2, 32, 4): (split s, query tile qt, batch b). Each CTA handles half the
// causal K-range of its query tile and writes unnormalized partials to scratch.
// K(kt+1) prefetched during PV-compute, V(kt) during S-compute (shared reg buffer).
#define SQS 129   // row stride for Q/K/V tiles (conflict-free for tx-strided reads)
#define SPS 65    // row stride for P tile

#define ATTN_SMEM ((2 * 64 * SQS + 64 * SPS) * 4)

__global__ __launch_bounds__(256, 2) void attn_kernel() {
    extern __shared__ float sm[];
    float* sQ  = sm;                    // 64 x SQS
    float* sKV = sm + 64 * SQS;         // 64 x SQS (K then V, reused)
    float* sP  = sKV + 64 * SQS;        // 64 x SPS

    int s  = blockIdx.x;                // split 0/1
    int qt = blockIdx.y;                // 0..31
    int b  = blockIdx.z;
    int q0 = qt * 64;
    int tid = threadIdx.x;
    int tx = tid & 15;
    int ty = tid >> 4;
    int r0 = ty * 4;

    int nk  = qt + 1;
    int nk2 = (nk + 1) >> 1;
    int kt0 = s ? nk2 : 0;
    int kt1 = s ? nk  : nk2;

    size_t part_base = ((size_t)(s * BB + b) * TT + q0) * DD;
    size_t ml_base   = (size_t)(s * BB + b) * TT + q0;

    if (kt0 >= kt1) {
        // empty split: neutral partials
        #pragma unroll
        for (int i = 0; i < 4; i++) {
            int row = r0 + i;
            #pragma unroll
            for (int jj = 0; jj < 8; jj++)
                g_Opart[part_base + (size_t)row * DD + tx + 16 * jj] = 0.0f;
            if (tx == 0) {
                g_Mpart[ml_base + row] = -1e30f;
                g_Lpart[ml_base + row] = 0.0f;
            }
        }
        return;
    }

    int ldr = tid >> 5;                 // 0..7 (row base for loader, +8u)
    int ldc = (tid & 31) * 4;           // col base for loader

    // load Q tile
    const float* Qg = g_Q + ((size_t)b * TT + q0) * DD;
    #pragma unroll
    for (int u = 0; u < 8; u++) {
        int r = ldr + 8 * u;
        float4 v = *(const float4*)&Qg[r * DD + ldc];
        float* dst = &sQ[r * SQS + ldc];
        dst[0] = v.x; dst[1] = v.y; dst[2] = v.z; dst[3] = v.w;
    }

    float O[4][8];
    #pragma unroll
    for (int i = 0; i < 4; i++)
        #pragma unroll
        for (int j = 0; j < 8; j++) O[i][j] = 0.0f;
    float m_i[4], l_i[4];
    #pragma unroll
    for (int i = 0; i < 4; i++) { m_i[i] = -1e30f; l_i[i] = 0.0f; }

    // prefetch first K tile into regs
    float4 pref[8];
    {
        const float* Kg = g_K + ((size_t)b * TT + kt0 * 64) * DD;
        #pragma unroll
        for (int u = 0; u < 8; u++)
            pref[u] = *(const float4*)&Kg[(ldr + 8 * u) * DD + ldc];
    }

    for (int kt = kt0; kt < kt1; kt++) {
        __syncthreads();   // prev PV done with sKV (also covers Q stores on iter 0)
        #pragma unroll
        for (int u = 0; u < 8; u++) {
            float* dst = &sKV[(ldr + 8 * u) * SQS + ldc];
            dst[0] = pref[u].x; dst[1] = pref[u].y; dst[2] = pref[u].z; dst[3] = pref[u].w;
        }
        __syncthreads();

        // prefetch V(kt) — overlaps S compute + softmax
        {
            const float* Vg = g_V + ((size_t)b * TT + kt * 64) * DD;
            #pragma unroll
            for (int u = 0; u < 8; u++)
                pref[u] = *(const float4*)&Vg[(ldr + 8 * u) * DD + ldc];
        }

        // S = Q K^T  (rows r0..r0+3, cols tx+16j)
        float acc[4][4] = {};
        #pragma unroll 4
        for (int d = 0; d < DD; d++) {
            float rq[4], rk[4];
            #pragma unroll
            for (int i = 0; i < 4; i++) rq[i] = sQ[(r0 + i) * SQS + d];
            #pragma unroll
            for (int j = 0; j < 4; j++) rk[j] = sKV[(tx + 16 * j) * SQS + d];
            #pragma unroll
            for (int i = 0; i < 4; i++)
                #pragma unroll
                for (int j = 0; j < 4; j++)
                    acc[i][j] += rq[i] * rk[j];
        }

        if (kt == qt) {  // causal mask on diagonal tile
            #pragma unroll
            for (int i = 0; i < 4; i++)
                #pragma unroll
                for (int j = 0; j < 4; j++)
                    if (tx + 16 * j > r0 + i) acc[i][j] = -1e30f;
        }

        // online softmax update
        #pragma unroll
        for (int i = 0; i < 4; i++) {
            float tmax = fmaxf(fmaxf(acc[i][0], acc[i][1]), fmaxf(acc[i][2], acc[i][3]));
            #pragma unroll
            for (int sh = 8; sh >= 1; sh >>= 1)
                tmax = fmaxf(tmax, __shfl_xor_sync(0xffffffffu, tmax, sh));
            float mnew = fmaxf(m_i[i], tmax);
            float corr = __expf(m_i[i] - mnew);
            float psum = 0.0f;
            #pragma unroll
            for (int j = 0; j < 4; j++) {
                acc[i][j] = __expf(acc[i][j] - mnew);
                psum += acc[i][j];
            }
            #pragma unroll
            for (int sh = 8; sh >= 1; sh >>= 1)
                psum += __shfl_xor_sync(0xffffffffu, psum, sh);
            l_i[i] = l_i[i] * corr + psum;
            m_i[i] = mnew;
            #pragma unroll
            for (int jj = 0; jj < 8; jj++) O[i][jj] *= corr;
            #pragma unroll
            for (int j = 0; j < 4; j++)
                sP[(r0 + i) * SPS + tx + 16 * j] = acc[i][j];
        }
        __syncthreads();   // S phase done: safe to overwrite sKV with V
        #pragma unroll
        for (int u = 0; u < 8; u++) {
            float* dst = &sKV[(ldr + 8 * u) * SQS + ldc];
            dst[0] = pref[u].x; dst[1] = pref[u].y; dst[2] = pref[u].z; dst[3] = pref[u].w;
        }
        __syncthreads();

        // prefetch K(kt+1) — overlaps PV compute
        if (kt + 1 < kt1) {
            const float* Kg = g_K + ((size_t)b * TT + (kt + 1) * 64) * DD;
            #pragma unroll
            for (int u = 0; u < 8; u++)
                pref[u] = *(const float4*)&Kg[(ldr + 8 * u) * DD + ldc];
        }

        // O += P @ V
        #pragma unroll 2
        for (int kk = 0; kk < 64; kk++) {
            float rp[4], rv[8];
            #pragma unroll
            for (int i = 0; i < 4; i++) rp[i] = sP[(r0 + i) * SPS + kk];
            #pragma unroll
            for (int jj = 0; jj < 8; jj++) rv[jj] = sKV[kk * SQS + tx + 16 * jj];
            #pragma unroll
            for (int i = 0; i < 4; i++)
                #pragma unroll
                for (int jj = 0; jj < 8; jj++)
                    O[i][jj] += rp[i] * rv[jj];
        }
    }

    // epilogue: write UNNORMALIZED partials + (m, l)
    #pragma unroll
    for (int i = 0; i < 4; i++) {
        int row = r0 + i;
        #pragma unroll
        for (int jj = 0; jj < 8; jj++)
            g_Opart[part_base + (size_t)row * DD + tx + 16 * jj] = O[i][jj];
        if (tx == 0) {
            g_Mpart[ml_base + row] = m_i[i];
            g_Lpart[ml_base + row] = l_i[i];
        }
    }
}

// ---------------- merge the two splits ----------------
__global__ __launch_bounds__(128) void merge_kernel(float* __restrict__ Out) {
    int row = blockIdx.x;           // 0 .. BB*TT-1
    int d   = threadIdx.x;          // 0 .. 127
    float m0 = g_Mpart[row];
    float m1 = g_Mpart[BB * TT + row];
    float l0 = g_Lpart[row];
    float l1 = g_Lpart[BB * TT + row];
    float m  = fmaxf(m0, m1);
    float a0 = __expf(m0 - m);
    float a1 = __expf(m1 - m);
    float inv = 1.0f / (a0 * l0 + a1 * l1);
    float o0 = g_Opart[(size_t)row * DD + d];
    float o1 = g_Opart[(size_t)(BB * TT + row) * DD + d];
    Out[(size_t)row * DD + d] = (a0 * o0 + a1 * o1) * inv;
}

// ---------------- launch ----------------
extern "C" void kernel_launch(void* const* d_in, const int* in_sizes, int n_in,
                              void* d_out, int out_size) {
    (void)in_sizes; (void)n_in; (void)out_size;
    const float* X  = (const float*)d_in[0];
    const float* Wq = (const float*)d_in[1];
    const float* Wk = (const float*)d_in[2];
    const float* Wv = (const float*)d_in[3];
    float* Out = (float*)d_out;

    rope_table_kernel<<<TT, DD / 2>>>();

    dim3 pg(BB * TT / 64, DD / 64, 3);
    proj_kernel<<<pg, 256>>>(X, Wq, Wk, Wv);

    cudaFuncSetAttribute(attn_kernel, cudaFuncAttributeMaxDynamicSharedMemorySize, ATTN_SMEM);
    dim3 ag(2, TT / 64, BB);
    attn_kernel<<<ag, 256, ATTN_SMEM>>>();

    merge_kernel<<<BB * TT, 128>>>(Out);
}

// round 6
// speedup vs baseline: 1.4505x; 1.2242x over previous
#include <cuda_runtime.h>
#include <cuda_bf16.h>
#include <stdint.h>
#include <math.h>

#define BB 4
#define TT 2048
#define EE 1024
#define DD 128

// ---------------- scratch (no allocations allowed) ----------------
__device__ float g_Q[BB * TT * DD];
__device__ float g_K[BB * TT * DD];
__device__ float g_V[BB * TT * DD];
__device__ float2 g_rope[TT * (DD / 2)];
// split-K partials: [split][b][t][d], unnormalized O plus per-row m,l
__device__ float g_Opart[2 * BB * TT * DD];
__device__ float g_Mpart[2 * BB * TT];
__device__ float g_Lpart[2 * BB * TT];

// ---------------- RoPE cos/sin table (double precision) ----------------
__global__ void rope_table_kernel() {
    int t = blockIdx.x;          // 0..2047
    int i = threadIdx.x;         // 0..63
    double freq = exp(-log(10000.0) * (double)(2 * i) / (double)DD);
    double ang = (double)t * freq;
    g_rope[t * (DD / 2) + i] = make_float2((float)cos(ang), (float)sin(ang));
}

// ---------------- QKV projection via bf16 split-precision tensor-core MMA ----
// C = X[8192,1024] @ W[128,1024]^T, fp32 in/out.
// x = hi + lo (bf16 each); C = Ah Bh + Ah Bl + Al Bh  (fp32 accum).
// BM=64, BN=128, BK=32. 256 threads = 8 warps, warp tile 32x32.
// smem row stride 40 bf16 (80B): fragment LDS banks = g*20+t mod 32, conflict-free.

#define PSTR 40

__device__ __forceinline__ void mma_bf16(float c[4], uint32_t a0, uint32_t a1,
                                         uint32_t a2, uint32_t a3,
                                         uint32_t b0, uint32_t b1) {
    asm volatile(
        "mma.sync.aligned.m16n8k16.row.col.f32.bf16.bf16.f32 "
        "{%0,%1,%2,%3}, {%4,%5,%6,%7}, {%8,%9}, {%0,%1,%2,%3};\n"
        : "+f"(c[0]), "+f"(c[1]), "+f"(c[2]), "+f"(c[3])
        : "r"(a0), "r"(a1), "r"(a2), "r"(a3), "r"(b0), "r"(b1));
}

__global__ __launch_bounds__(256, 2) void proj_mma_kernel(
    const float* __restrict__ X,
    const float* __restrict__ Wq,
    const float* __restrict__ Wk,
    const float* __restrict__ Wv)
{
    const float* W;
    float* Out;
    int do_rope;
    float scale;
    int z = blockIdx.y;
    if (z == 0)      { W = Wq; Out = g_Q; do_rope = 1; scale = 0.08838834764831845f; }
    else if (z == 1) { W = Wk; Out = g_K; do_rope = 1; scale = 1.0f; }
    else             { W = Wv; Out = g_V; do_rope = 0; scale = 1.0f; }

    __shared__ __nv_bfloat16 sAh[64][PSTR];
    __shared__ __nv_bfloat16 sAl[64][PSTR];
    __shared__ __nv_bfloat16 sBh[128][PSTR];
    __shared__ __nv_bfloat16 sBl[128][PSTR];

    int tid  = threadIdx.x;
    int warp = tid >> 5;
    int lane = tid & 31;
    int wm = warp & 1;            // 2 m-tiles of 32
    int wn = warp >> 1;           // 4 n-tiles of 32
    int g  = lane >> 2;           // 0..7
    int t  = lane & 3;            // 0..3
    int mb = blockIdx.x * 64;

    float c[2][4][4];
    #pragma unroll
    for (int i = 0; i < 2; i++)
        #pragma unroll
        for (int j = 0; j < 4; j++)
            #pragma unroll
            for (int r = 0; r < 4; r++) c[i][j][r] = 0.0f;

    // loader mapping: X tile 64x32 -> 512 float4; W tile 128x32 -> 1024 float4
    int ar[2], ac[2], br[4], bc[4];
    #pragma unroll
    for (int u = 0; u < 2; u++) {
        int idx = tid + 256 * u;
        ar[u] = idx >> 3; ac[u] = (idx & 7) * 4;
    }
    #pragma unroll
    for (int u = 0; u < 4; u++) {
        int idx = tid + 256 * u;
        br[u] = idx >> 3; bc[u] = (idx & 7) * 4;
    }

    float4 pfA[2], pfB[4];
    #pragma unroll
    for (int u = 0; u < 2; u++)
        pfA[u] = *(const float4*)&X[(size_t)(mb + ar[u]) * EE + ac[u]];
    #pragma unroll
    for (int u = 0; u < 4; u++)
        pfB[u] = *(const float4*)&W[(size_t)br[u] * EE + bc[u]];

    for (int k0 = 0; k0 < EE; k0 += 32) {
        __syncthreads();
        #pragma unroll
        for (int u = 0; u < 2; u++) {
            float v[4] = {pfA[u].x, pfA[u].y, pfA[u].z, pfA[u].w};
            #pragma unroll
            for (int e = 0; e < 4; e++) {
                __nv_bfloat16 hi = __float2bfloat16(v[e]);
                sAh[ar[u]][ac[u] + e] = hi;
                sAl[ar[u]][ac[u] + e] = __float2bfloat16(v[e] - __bfloat162float(hi));
            }
        }
        #pragma unroll
        for (int u = 0; u < 4; u++) {
            float v[4] = {pfB[u].x, pfB[u].y, pfB[u].z, pfB[u].w};
            #pragma unroll
            for (int e = 0; e < 4; e++) {
                __nv_bfloat16 hi = __float2bfloat16(v[e]);
                sBh[br[u]][bc[u] + e] = hi;
                sBl[br[u]][bc[u] + e] = __float2bfloat16(v[e] - __bfloat162float(hi));
            }
        }
        __syncthreads();

        if (k0 + 32 < EE) {   // prefetch next slab; overlaps MMA below
            #pragma unroll
            for (int u = 0; u < 2; u++)
                pfA[u] = *(const float4*)&X[(size_t)(mb + ar[u]) * EE + k0 + 32 + ac[u]];
            #pragma unroll
            for (int u = 0; u < 4; u++)
                pfB[u] = *(const float4*)&W[(size_t)br[u] * EE + k0 + 32 + bc[u]];
        }

        #pragma unroll
        for (int h = 0; h < 2; h++) {
            int kb = h * 16 + 2 * t;
            uint32_t ah[2][4], al[2][4], bh[4][2], bl[4][2];
            #pragma unroll
            for (int i = 0; i < 2; i++) {
                int r0 = wm * 32 + i * 16 + g;
                ah[i][0] = *(const uint32_t*)&sAh[r0][kb];
                ah[i][1] = *(const uint32_t*)&sAh[r0 + 8][kb];
                ah[i][2] = *(const uint32_t*)&sAh[r0][kb + 8];
                ah[i][3] = *(const uint32_t*)&sAh[r0 + 8][kb + 8];
                al[i][0] = *(const uint32_t*)&sAl[r0][kb];
                al[i][1] = *(const uint32_t*)&sAl[r0 + 8][kb];
                al[i][2] = *(const uint32_t*)&sAl[r0][kb + 8];
                al[i][3] = *(const uint32_t*)&sAl[r0 + 8][kb + 8];
            }
            #pragma unroll
            for (int j = 0; j < 4; j++) {
                int n0 = wn * 32 + j * 8 + g;
                bh[j][0] = *(const uint32_t*)&sBh[n0][kb];
                bh[j][1] = *(const uint32_t*)&sBh[n0][kb + 8];
                bl[j][0] = *(const uint32_t*)&sBl[n0][kb];
                bl[j][1] = *(const uint32_t*)&sBl[n0][kb + 8];
            }
            #pragma unroll
            for (int i = 0; i < 2; i++)
                #pragma unroll
                for (int j = 0; j < 4; j++) {
                    mma_bf16(c[i][j], ah[i][0], ah[i][1], ah[i][2], ah[i][3],
                             bh[j][0], bh[j][1]);
                    mma_bf16(c[i][j], ah[i][0], ah[i][1], ah[i][2], ah[i][3],
                             bl[j][0], bl[j][1]);
                    mma_bf16(c[i][j], al[i][0], al[i][1], al[i][2], al[i][3],
                             bh[j][0], bh[j][1]);
                }
        }
    }

    // epilogue: RoPE (pairs are exactly c0,c1 / c2,c3) + store fp32
    #pragma unroll
    for (int i = 0; i < 2; i++) {
        int row0 = mb + wm * 32 + i * 16 + g;
        #pragma unroll
        for (int j = 0; j < 4; j++) {
            int col = wn * 32 + j * 8 + 2 * t;
            float p0 = c[i][j][0], p1 = c[i][j][1];
            float q0 = c[i][j][2], q1 = c[i][j][3];
            if (do_rope) {
                int t0 = row0 & (TT - 1);
                int t1 = (row0 + 8) & (TT - 1);
                float2 cs0 = g_rope[t0 * (DD / 2) + (col >> 1)];
                float2 cs1 = g_rope[t1 * (DD / 2) + (col >> 1)];
                float a = p0, b = p1;
                p0 = (a * cs0.x - b * cs0.y) * scale;
                p1 = (a * cs0.y + b * cs0.x) * scale;
                a = q0; b = q1;
                q0 = (a * cs1.x - b * cs1.y) * scale;
                q1 = (a * cs1.y + b * cs1.x) * scale;
            }
            *(float2*)&Out[(size_t)row0 * DD + col] = make_float2(p0, p1);
            *(float2*)&Out[(size_t)(row0 + 8) * DD + col] = make_float2(q0, q1);
        }
    }
}

// ---------------- split-K flash attention (fp32) ----------------
#define SQS 129
#define SPS 65

#define ATTN_SMEM ((2 * 64 * SQS + 64 * SPS) * 4)

__global__ __launch_bounds__(256, 2) void attn_kernel() {
    extern __shared__ float sm[];
    float* sQ  = sm;                    // 64 x SQS
    float* sKV = sm + 64 * SQS;         // 64 x SQS (K then V, reused)
    float* sP  = sKV + 64 * SQS;        // 64 x SPS

    int s  = blockIdx.x;                // split 0/1
    int qt = blockIdx.y;                // 0..31
    int b  = blockIdx.z;
    int q0 = qt * 64;
    int tid = threadIdx.x;
    int tx = tid & 15;
    int ty = tid >> 4;
    int r0 = ty * 4;

    int nk  = qt + 1;
    int nk2 = (nk + 1) >> 1;
    int kt0 = s ? nk2 : 0;
    int kt1 = s ? nk  : nk2;

    size_t part_base = ((size_t)(s * BB + b) * TT + q0) * DD;
    size_t ml_base   = (size_t)(s * BB + b) * TT + q0;

    if (kt0 >= kt1) {
        #pragma unroll
        for (int i = 0; i < 4; i++) {
            int row = r0 + i;
            #pragma unroll
            for (int jj = 0; jj < 8; jj++)
                g_Opart[part_base + (size_t)row * DD + tx + 16 * jj] = 0.0f;
            if (tx == 0) {
                g_Mpart[ml_base + row] = -1e30f;
                g_Lpart[ml_base + row] = 0.0f;
            }
        }
        return;
    }

    int ldr = tid >> 5;
    int ldc = (tid & 31) * 4;

    const float* Qg = g_Q + ((size_t)b * TT + q0) * DD;
    #pragma unroll
    for (int u = 0; u < 8; u++) {
        int r = ldr + 8 * u;
        float4 v = *(const float4*)&Qg[r * DD + ldc];
        float* dst = &sQ[r * SQS + ldc];
        dst[0] = v.x; dst[1] = v.y; dst[2] = v.z; dst[3] = v.w;
    }

    float O[4][8];
    #pragma unroll
    for (int i = 0; i < 4; i++)
        #pragma unroll
        for (int j = 0; j < 8; j++) O[i][j] = 0.0f;
    float m_i[4], l_i[4];
    #pragma unroll
    for (int i = 0; i < 4; i++) { m_i[i] = -1e30f; l_i[i] = 0.0f; }

    float4 pref[8];
    {
        const float* Kg = g_K + ((size_t)b * TT + kt0 * 64) * DD;
        #pragma unroll
        for (int u = 0; u < 8; u++)
            pref[u] = *(const float4*)&Kg[(ldr + 8 * u) * DD + ldc];
    }

    for (int kt = kt0; kt < kt1; kt++) {
        __syncthreads();
        #pragma unroll
        for (int u = 0; u < 8; u++) {
            float* dst = &sKV[(ldr + 8 * u) * SQS + ldc];
            dst[0] = pref[u].x; dst[1] = pref[u].y; dst[2] = pref[u].z; dst[3] = pref[u].w;
        }
        __syncthreads();

        {
            const float* Vg = g_V + ((size_t)b * TT + kt * 64) * DD;
            #pragma unroll
            for (int u = 0; u < 8; u++)
                pref[u] = *(const float4*)&Vg[(ldr + 8 * u) * DD + ldc];
        }

        float acc[4][4] = {};
        #pragma unroll 4
        for (int d = 0; d < DD; d++) {
            float rq[4], rk[4];
            #pragma unroll
            for (int i = 0; i < 4; i++) rq[i] = sQ[(r0 + i) * SQS + d];
            #pragma unroll
            for (int j = 0; j < 4; j++) rk[j] = sKV[(tx + 16 * j) * SQS + d];
            #pragma unroll
            for (int i = 0; i < 4; i++)
                #pragma unroll
                for (int j = 0; j < 4; j++)
                    acc[i][j] += rq[i] * rk[j];
        }

        if (kt == qt) {
            #pragma unroll
            for (int i = 0; i < 4; i++)
                #pragma unroll
                for (int j = 0; j < 4; j++)
                    if (tx + 16 * j > r0 + i) acc[i][j] = -1e30f;
        }

        #pragma unroll
        for (int i = 0; i < 4; i++) {
            float tmax = fmaxf(fmaxf(acc[i][0], acc[i][1]), fmaxf(acc[i][2], acc[i][3]));
            #pragma unroll
            for (int sh = 8; sh >= 1; sh >>= 1)
                tmax = fmaxf(tmax, __shfl_xor_sync(0xffffffffu, tmax, sh));
            float mnew = fmaxf(m_i[i], tmax);
            float corr = __expf(m_i[i] - mnew);
            float psum = 0.0f;
            #pragma unroll
            for (int j = 0; j < 4; j++) {
                acc[i][j] = __expf(acc[i][j] - mnew);
                psum += acc[i][j];
            }
            #pragma unroll
            for (int sh = 8; sh >= 1; sh >>= 1)
                psum += __shfl_xor_sync(0xffffffffu, psum, sh);
            l_i[i] = l_i[i] * corr + psum;
            m_i[i] = mnew;
            #pragma unroll
            for (int jj = 0; jj < 8; jj++) O[i][jj] *= corr;
            #pragma unroll
            for (int j = 0; j < 4; j++)
                sP[(r0 + i) * SPS + tx + 16 * j] = acc[i][j];
        }
        __syncthreads();
        #pragma unroll
        for (int u = 0; u < 8; u++) {
            float* dst = &sKV[(ldr + 8 * u) * SQS + ldc];
            dst[0] = pref[u].x; dst[1] = pref[u].y; dst[2] = pref[u].z; dst[3] = pref[u].w;
        }
        __syncthreads();

        if (kt + 1 < kt1) {
            const float* Kg = g_K + ((size_t)b * TT + (kt + 1) * 64) * DD;
            #pragma unroll
            for (int u = 0; u < 8; u++)
                pref[u] = *(const float4*)&Kg[(ldr + 8 * u) * DD + ldc];
        }

        #pragma unroll 2
        for (int kk = 0; kk < 64; kk++) {
            float rp[4], rv[8];
            #pragma unroll
            for (int i = 0; i < 4; i++) rp[i] = sP[(r0 + i) * SPS + kk];
            #pragma unroll
            for (int jj = 0; jj < 8; jj++) rv[jj] = sKV[kk * SQS + tx + 16 * jj];
            #pragma unroll
            for (int i = 0; i < 4; i++)
                #pragma unroll
                for (int jj = 0; jj < 8; jj++)
                    O[i][jj] += rp[i] * rv[jj];
        }
    }

    #pragma unroll
    for (int i = 0; i < 4; i++) {
        int row = r0 + i;
        #pragma unroll
        for (int jj = 0; jj < 8; jj++)
            g_Opart[part_base + (size_t)row * DD + tx + 16 * jj] = O[i][jj];
        if (tx == 0) {
            g_Mpart[ml_base + row] = m_i[i];
            g_Lpart[ml_base + row] = l_i[i];
        }
    }
}

// ---------------- merge the two splits ----------------
__global__ __launch_bounds__(128) void merge_kernel(float* __restrict__ Out) {
    int row = blockIdx.x;
    int d   = threadIdx.x;
    float m0 = g_Mpart[row];
    float m1 = g_Mpart[BB * TT + row];
    float l0 = g_Lpart[row];
    float l1 = g_Lpart[BB * TT + row];
    float m  = fmaxf(m0, m1);
    float a0 = __expf(m0 - m);
    float a1 = __expf(m1 - m);
    float inv = 1.0f / (a0 * l0 + a1 * l1);
    float o0 = g_Opart[(size_t)row * DD + d];
    float o1 = g_Opart[(size_t)(BB * TT + row) * DD + d];
    Out[(size_t)row * DD + d] = (a0 * o0 + a1 * o1) * inv;
}

// ---------------- launch ----------------
extern "C" void kernel_launch(void* const* d_in, const int* in_sizes, int n_in,
                              void* d_out, int out_size) {
    (void)in_sizes; (void)n_in; (void)out_size;
    const float* X  = (const float*)d_in[0];
    const float* Wq = (const float*)d_in[1];
    const float* Wk = (const float*)d_in[2];
    const float* Wv = (const float*)d_in[3];
    float* Out = (float*)d_out;

    rope_table_kernel<<<TT, DD / 2>>>();

    dim3 pg(BB * TT / 64, 3);
    proj_mma_kernel<<<pg, 256>>>(X, Wq, Wk, Wv);

    cudaFuncSetAttribute(attn_kernel, cudaFuncAttributeMaxDynamicSharedMemorySize, ATTN_SMEM);
    dim3 ag(2, TT / 64, BB);
    attn_kernel<<<ag, 256, ATTN_SMEM>>>();

    merge_kernel<<<BB * TT, 128>>>(Out);
}

// round 7
// speedup vs baseline: 2.9603x; 2.0409x over previous
#include <cuda_runtime.h>
#include <cuda_bf16.h>
#include <stdint.h>
#include <math.h>

#define BB 4
#define TT 2048
#define EE 1024
#define DD 128

// ---------------- scratch (no allocations allowed) ----------------
// Q/K/V stored as split-precision bf16 planes (hi + lo), layout [b][t][d]
__device__ __nv_bfloat16 g_Qh[BB * TT * DD];
__device__ __nv_bfloat16 g_Ql[BB * TT * DD];
__device__ __nv_bfloat16 g_Kh[BB * TT * DD];
__device__ __nv_bfloat16 g_Kl[BB * TT * DD];
__device__ __nv_bfloat16 g_Vh[BB * TT * DD];
__device__ __nv_bfloat16 g_Vl[BB * TT * DD];
__device__ float2 g_rope[TT * (DD / 2)];
// split-K partials: [split][b][t][d], unnormalized O plus per-row m,l
__device__ float g_Opart[2 * BB * TT * DD];
__device__ float g_Mpart[2 * BB * TT];
__device__ float g_Lpart[2 * BB * TT];

// ---------------- RoPE cos/sin table (double precision) ----------------
__global__ void rope_table_kernel() {
    int t = blockIdx.x;
    int i = threadIdx.x;
    double freq = exp(-log(10000.0) * (double)(2 * i) / (double)DD);
    double ang = (double)t * freq;
    g_rope[t * (DD / 2) + i] = make_float2((float)cos(ang), (float)sin(ang));
}

// ---------------- common MMA / ldmatrix helpers ----------------
__device__ __forceinline__ void mma_bf16(float c[4], uint32_t a0, uint32_t a1,
                                         uint32_t a2, uint32_t a3,
                                         uint32_t b0, uint32_t b1) {
    asm volatile(
        "mma.sync.aligned.m16n8k16.row.col.f32.bf16.bf16.f32 "
        "{%0,%1,%2,%3}, {%4,%5,%6,%7}, {%8,%9}, {%0,%1,%2,%3};\n"
        : "+f"(c[0]), "+f"(c[1]), "+f"(c[2]), "+f"(c[3])
        : "r"(a0), "r"(a1), "r"(a2), "r"(a3), "r"(b0), "r"(b1));
}

__device__ __forceinline__ void ldsm4(uint32_t r[4], uint32_t addr) {
    asm volatile("ldmatrix.sync.aligned.m8n8.x4.shared.b16 {%0,%1,%2,%3}, [%4];"
                 : "=r"(r[0]), "=r"(r[1]), "=r"(r[2]), "=r"(r[3]) : "r"(addr));
}
__device__ __forceinline__ void ldsm4t(uint32_t r[4], uint32_t addr) {
    asm volatile("ldmatrix.sync.aligned.m8n8.x4.trans.shared.b16 {%0,%1,%2,%3}, [%4];"
                 : "=r"(r[0]), "=r"(r[1]), "=r"(r[2]), "=r"(r[3]) : "r"(addr));
}

// ---------------- QKV projection (bf16 split MMA) -> hi/lo bf16 planes -----
#define PSTR 40

__global__ __launch_bounds__(256, 2) void proj_mma_kernel(
    const float* __restrict__ X,
    const float* __restrict__ Wq,
    const float* __restrict__ Wk,
    const float* __restrict__ Wv)
{
    const float* W;
    __nv_bfloat16 *OH, *OL;
    int do_rope;
    float scale;
    int z = blockIdx.y;
    if (z == 0)      { W = Wq; OH = g_Qh; OL = g_Ql; do_rope = 1; scale = 0.08838834764831845f; }
    else if (z == 1) { W = Wk; OH = g_Kh; OL = g_Kl; do_rope = 1; scale = 1.0f; }
    else             { W = Wv; OH = g_Vh; OL = g_Vl; do_rope = 0; scale = 1.0f; }

    __shared__ __nv_bfloat16 sAh[64][PSTR];
    __shared__ __nv_bfloat16 sAl[64][PSTR];
    __shared__ __nv_bfloat16 sBh[128][PSTR];
    __shared__ __nv_bfloat16 sBl[128][PSTR];

    int tid  = threadIdx.x;
    int warp = tid >> 5;
    int lane = tid & 31;
    int wm = warp & 1;
    int wn = warp >> 1;
    int g  = lane >> 2;
    int t  = lane & 3;
    int mb = blockIdx.x * 64;

    float c[2][4][4];
    #pragma unroll
    for (int i = 0; i < 2; i++)
        #pragma unroll
        for (int j = 0; j < 4; j++)
            #pragma unroll
            for (int r = 0; r < 4; r++) c[i][j][r] = 0.0f;

    int ar[2], ac[2], br[4], bc[4];
    #pragma unroll
    for (int u = 0; u < 2; u++) {
        int idx = tid + 256 * u;
        ar[u] = idx >> 3; ac[u] = (idx & 7) * 4;
    }
    #pragma unroll
    for (int u = 0; u < 4; u++) {
        int idx = tid + 256 * u;
        br[u] = idx >> 3; bc[u] = (idx & 7) * 4;
    }

    float4 pfA[2], pfB[4];
    #pragma unroll
    for (int u = 0; u < 2; u++)
        pfA[u] = *(const float4*)&X[(size_t)(mb + ar[u]) * EE + ac[u]];
    #pragma unroll
    for (int u = 0; u < 4; u++)
        pfB[u] = *(const float4*)&W[(size_t)br[u] * EE + bc[u]];

    for (int k0 = 0; k0 < EE; k0 += 32) {
        __syncthreads();
        #pragma unroll
        for (int u = 0; u < 2; u++) {
            float v[4] = {pfA[u].x, pfA[u].y, pfA[u].z, pfA[u].w};
            #pragma unroll
            for (int e = 0; e < 4; e++) {
                __nv_bfloat16 hi = __float2bfloat16(v[e]);
                sAh[ar[u]][ac[u] + e] = hi;
                sAl[ar[u]][ac[u] + e] = __float2bfloat16(v[e] - __bfloat162float(hi));
            }
        }
        #pragma unroll
        for (int u = 0; u < 4; u++) {
            float v[4] = {pfB[u].x, pfB[u].y, pfB[u].z, pfB[u].w};
            #pragma unroll
            for (int e = 0; e < 4; e++) {
                __nv_bfloat16 hi = __float2bfloat16(v[e]);
                sBh[br[u]][bc[u] + e] = hi;
                sBl[br[u]][bc[u] + e] = __float2bfloat16(v[e] - __bfloat162float(hi));
            }
        }
        __syncthreads();

        if (k0 + 32 < EE) {
            #pragma unroll
            for (int u = 0; u < 2; u++)
                pfA[u] = *(const float4*)&X[(size_t)(mb + ar[u]) * EE + k0 + 32 + ac[u]];
            #pragma unroll
            for (int u = 0; u < 4; u++)
                pfB[u] = *(const float4*)&W[(size_t)br[u] * EE + k0 + 32 + bc[u]];
        }

        #pragma unroll
        for (int h = 0; h < 2; h++) {
            int kb = h * 16 + 2 * t;
            uint32_t ah[2][4], al[2][4], bh[4][2], bl[4][2];
            #pragma unroll
            for (int i = 0; i < 2; i++) {
                int r0 = wm * 32 + i * 16 + g;
                ah[i][0] = *(const uint32_t*)&sAh[r0][kb];
                ah[i][1] = *(const uint32_t*)&sAh[r0 + 8][kb];
                ah[i][2] = *(const uint32_t*)&sAh[r0][kb + 8];
                ah[i][3] = *(const uint32_t*)&sAh[r0 + 8][kb + 8];
                al[i][0] = *(const uint32_t*)&sAl[r0][kb];
                al[i][1] = *(const uint32_t*)&sAl[r0 + 8][kb];
                al[i][2] = *(const uint32_t*)&sAl[r0][kb + 8];
                al[i][3] = *(const uint32_t*)&sAl[r0 + 8][kb + 8];
            }
            #pragma unroll
            for (int j = 0; j < 4; j++) {
                int n0 = wn * 32 + j * 8 + g;
                bh[j][0] = *(const uint32_t*)&sBh[n0][kb];
                bh[j][1] = *(const uint32_t*)&sBh[n0][kb + 8];
                bl[j][0] = *(const uint32_t*)&sBl[n0][kb];
                bl[j][1] = *(const uint32_t*)&sBl[n0][kb + 8];
            }
            #pragma unroll
            for (int i = 0; i < 2; i++)
                #pragma unroll
                for (int j = 0; j < 4; j++) {
                    mma_bf16(c[i][j], ah[i][0], ah[i][1], ah[i][2], ah[i][3],
                             bh[j][0], bh[j][1]);
                    mma_bf16(c[i][j], ah[i][0], ah[i][1], ah[i][2], ah[i][3],
                             bl[j][0], bl[j][1]);
                    mma_bf16(c[i][j], al[i][0], al[i][1], al[i][2], al[i][3],
                             bh[j][0], bh[j][1]);
                }
        }
    }

    // epilogue: RoPE on (c0,c1)/(c2,c3) pairs, then split to bf16 hi/lo planes
    #pragma unroll
    for (int i = 0; i < 2; i++) {
        int row0 = mb + wm * 32 + i * 16 + g;
        #pragma unroll
        for (int j = 0; j < 4; j++) {
            int col = wn * 32 + j * 8 + 2 * t;
            float p0 = c[i][j][0], p1 = c[i][j][1];
            float q0 = c[i][j][2], q1 = c[i][j][3];
            if (do_rope) {
                int t0 = row0 & (TT - 1);
                int t1 = (row0 + 8) & (TT - 1);
                float2 cs0 = g_rope[t0 * (DD / 2) + (col >> 1)];
                float2 cs1 = g_rope[t1 * (DD / 2) + (col >> 1)];
                float a = p0, b = p1;
                p0 = (a * cs0.x - b * cs0.y) * scale;
                p1 = (a * cs0.y + b * cs0.x) * scale;
                a = q0; b = q1;
                q0 = (a * cs1.x - b * cs1.y) * scale;
                q1 = (a * cs1.y + b * cs1.x) * scale;
            }
            __nv_bfloat16 h0 = __float2bfloat16(p0);
            __nv_bfloat16 h1 = __float2bfloat16(p1);
            __nv_bfloat16 l0 = __float2bfloat16(p0 - __bfloat162float(h0));
            __nv_bfloat16 l1 = __float2bfloat16(p1 - __bfloat162float(h1));
            *(__nv_bfloat162*)&OH[(size_t)row0 * DD + col] = __nv_bfloat162(h0, h1);
            *(__nv_bfloat162*)&OL[(size_t)row0 * DD + col] = __nv_bfloat162(l0, l1);
            h0 = __float2bfloat16(q0);
            h1 = __float2bfloat16(q1);
            l0 = __float2bfloat16(q0 - __bfloat162float(h0));
            l1 = __float2bfloat16(q1 - __bfloat162float(h1));
            *(__nv_bfloat162*)&OH[(size_t)(row0 + 8) * DD + col] = __nv_bfloat162(h0, h1);
            *(__nv_bfloat162*)&OL[(size_t)(row0 + 8) * DD + col] = __nv_bfloat162(l0, l1);
        }
    }
}

// ---------------- tensor-core flash attention (split-K 2) ----------------
// 256 thr = 8 warps: wr=warp>>1 (16 query rows), wc=warp&1 (32-key half).
// smem bf16 (stride 136): Qh, Ql, KVh, KVl tiles; + float reduce buffers.
#define KSTR 136
#define QH_OFF 0
#define QL_OFF 8704
#define KH_OFF 17408
#define KL_OFF 26112
#define RED_BYTES (34816 * 2)
#define ATTN_SMEM2 (RED_BYTES + 1024)

__global__ __launch_bounds__(256, 1) void attn_mma_kernel() {
    extern __shared__ __align__(16) char smraw[];
    __nv_bfloat16* sb = (__nv_bfloat16*)smraw;
    float* sRmax = (float*)(smraw + RED_BYTES);   // [2][64]
    float* sRsum = sRmax + 128;                   // [2][64]
    uint32_t sbase = (uint32_t)__cvta_generic_to_shared(sb);

    int s  = blockIdx.x;
    int qt = 31 - blockIdx.y;       // heavy tiles first
    int b  = blockIdx.z;
    int q0 = qt * 64;
    int tid  = threadIdx.x;
    int warp = tid >> 5;
    int lane = tid & 31;
    int wr = warp >> 1;
    int wc = warp & 1;
    int g  = lane >> 2;
    int t_ = lane & 3;
    int qrow = wr * 16;
    int kb   = wc * 32;
    uint32_t lrow16 = lane & 15;
    uint32_t lhalf  = lane >> 4;

    int nk  = qt + 1;
    int nk2 = (nk + 1) >> 1;
    int kt0 = s ? nk2 : 0;
    int kt1 = s ? nk  : nk2;

    size_t part_base = ((size_t)(s * BB + b) * TT + q0) * DD;
    size_t ml_base   = (size_t)(s * BB + b) * TT + q0;

    if (kt0 >= kt1) {               // empty split: neutral partials
        for (int i = tid; i < 64 * DD; i += 256)
            g_Opart[part_base + (i >> 7) * (size_t)DD + (i & 127)] = 0.0f;
        if (tid < 64) {
            g_Mpart[ml_base + tid] = -1e30f;
            g_Lpart[ml_base + tid] = 0.0f;
        }
        return;
    }

    // loader mapping for 64x128 bf16 tiles (1024 uint4 per plane)
    int lr[4], lc[4];
    #pragma unroll
    for (int u = 0; u < 4; u++) {
        int idx = tid + 256 * u;
        lr[u] = idx >> 4; lc[u] = idx & 15;
    }

    // load Q tile (both planes) into smem
    {
        const uint4* Qh4 = (const uint4*)(g_Qh + ((size_t)b * TT + q0) * DD);
        const uint4* Ql4 = (const uint4*)(g_Ql + ((size_t)b * TT + q0) * DD);
        #pragma unroll
        for (int u = 0; u < 4; u++) {
            *(uint4*)(sb + QH_OFF + lr[u] * KSTR + lc[u] * 8) = Qh4[lr[u] * 16 + lc[u]];
            *(uint4*)(sb + QL_OFF + lr[u] * KSTR + lc[u] * 8) = Ql4[lr[u] * 16 + lc[u]];
        }
    }

    float o[16][4];
    #pragma unroll
    for (int nf = 0; nf < 16; nf++)
        #pragma unroll
        for (int r = 0; r < 4; r++) o[nf][r] = 0.0f;
    float m0 = -1e30f, m1 = -1e30f, l0 = 0.0f, l1 = 0.0f;

    // prefetch first K tile
    uint4 pref[8];
    {
        const uint4* Kh4 = (const uint4*)(g_Kh + ((size_t)b * TT + kt0 * 64) * DD);
        const uint4* Kl4 = (const uint4*)(g_Kl + ((size_t)b * TT + kt0 * 64) * DD);
        #pragma unroll
        for (int u = 0; u < 4; u++) {
            pref[u]     = Kh4[lr[u] * 16 + lc[u]];
            pref[4 + u] = Kl4[lr[u] * 16 + lc[u]];
        }
    }

    for (int kt = kt0; kt < kt1; kt++) {
        __syncthreads();            // (D) prev V reads done (covers Q stores iter 0)
        #pragma unroll
        for (int u = 0; u < 4; u++) {
            *(uint4*)(sb + KH_OFF + lr[u] * KSTR + lc[u] * 8) = pref[u];
            *(uint4*)(sb + KL_OFF + lr[u] * KSTR + lc[u] * 8) = pref[4 + u];
        }
        __syncthreads();            // (E)

        // prefetch V(kt) — overlaps S MMA
        {
            const uint4* Vh4 = (const uint4*)(g_Vh + ((size_t)b * TT + kt * 64) * DD);
            const uint4* Vl4 = (const uint4*)(g_Vl + ((size_t)b * TT + kt * 64) * DD);
            #pragma unroll
            for (int u = 0; u < 4; u++) {
                pref[u]     = Vh4[lr[u] * 16 + lc[u]];
                pref[4 + u] = Vl4[lr[u] * 16 + lc[u]];
            }
        }

        // ---- S = Q K^T : warp computes 16 rows x 32 keys ----
        float sa[4][4];
        #pragma unroll
        for (int nf = 0; nf < 4; nf++)
            #pragma unroll
            for (int r = 0; r < 4; r++) sa[nf][r] = 0.0f;

        #pragma unroll
        for (int kf = 0; kf < 8; kf++) {
            uint32_t qh[4], ql[4];
            uint32_t aq = sbase + (QH_OFF + (qrow + lrow16) * KSTR + kf * 16 + lhalf * 8) * 2;
            ldsm4(qh, aq);
            ldsm4(ql, aq + (QL_OFF - QH_OFF) * 2);
            #pragma unroll
            for (int nfp = 0; nfp < 2; nfp++) {
                uint32_t kh[4], kl[4];
                uint32_t ak = sbase + (KH_OFF + (kb + nfp * 16 + lrow16) * KSTR + kf * 16 + lhalf * 8) * 2;
                ldsm4(kh, ak);
                ldsm4(kl, ak + (KL_OFF - KH_OFF) * 2);
                // nf = 2nfp: frag (r0,r2); nf+1: (r1,r3)
                mma_bf16(sa[2 * nfp], qh[0], qh[1], qh[2], qh[3], kh[0], kh[2]);
                mma_bf16(sa[2 * nfp], qh[0], qh[1], qh[2], qh[3], kl[0], kl[2]);
                mma_bf16(sa[2 * nfp], ql[0], ql[1], ql[2], ql[3], kh[0], kh[2]);
                mma_bf16(sa[2 * nfp + 1], qh[0], qh[1], qh[2], qh[3], kh[1], kh[3]);
                mma_bf16(sa[2 * nfp + 1], qh[0], qh[1], qh[2], qh[3], kl[1], kl[3]);
                mma_bf16(sa[2 * nfp + 1], ql[0], ql[1], ql[2], ql[3], kh[1], kh[3]);
            }
        }

        // causal mask on diagonal tile
        if (kt == qt) {
            int qi0 = q0 + qrow + g;
            int qi1 = qi0 + 8;
            int k0g = kt * 64 + kb + 2 * t_;
            #pragma unroll
            for (int nf = 0; nf < 4; nf++) {
                int kc = k0g + 8 * nf;
                if (kc     > qi0) sa[nf][0] = -1e30f;
                if (kc + 1 > qi0) sa[nf][1] = -1e30f;
                if (kc     > qi1) sa[nf][2] = -1e30f;
                if (kc + 1 > qi1) sa[nf][3] = -1e30f;
            }
        }

        // ---- online softmax (cross-warp over the two key halves) ----
        float pm0 = -1e30f, pm1 = -1e30f;
        #pragma unroll
        for (int nf = 0; nf < 4; nf++) {
            pm0 = fmaxf(pm0, fmaxf(sa[nf][0], sa[nf][1]));
            pm1 = fmaxf(pm1, fmaxf(sa[nf][2], sa[nf][3]));
        }
        #pragma unroll
        for (int sh = 1; sh <= 2; sh <<= 1) {
            pm0 = fmaxf(pm0, __shfl_xor_sync(0xffffffffu, pm0, sh));
            pm1 = fmaxf(pm1, __shfl_xor_sync(0xffffffffu, pm1, sh));
        }
        if (t_ == 0) {
            sRmax[wc * 64 + qrow + g]     = pm0;
            sRmax[wc * 64 + qrow + g + 8] = pm1;
        }
        __syncthreads();            // (A)
        float tm0 = fmaxf(pm0, sRmax[(1 - wc) * 64 + qrow + g]);
        float tm1 = fmaxf(pm1, sRmax[(1 - wc) * 64 + qrow + g + 8]);
        float mn0 = fmaxf(m0, tm0), mn1 = fmaxf(m1, tm1);
        float corr0 = __expf(m0 - mn0), corr1 = __expf(m1 - mn1);

        float ps0 = 0.0f, ps1 = 0.0f;
        #pragma unroll
        for (int nf = 0; nf < 4; nf++) {
            sa[nf][0] = __expf(sa[nf][0] - mn0);
            sa[nf][1] = __expf(sa[nf][1] - mn0);
            sa[nf][2] = __expf(sa[nf][2] - mn1);
            sa[nf][3] = __expf(sa[nf][3] - mn1);
            ps0 += sa[nf][0] + sa[nf][1];
            ps1 += sa[nf][2] + sa[nf][3];
        }
        #pragma unroll
        for (int sh = 1; sh <= 2; sh <<= 1) {
            ps0 += __shfl_xor_sync(0xffffffffu, ps0, sh);
            ps1 += __shfl_xor_sync(0xffffffffu, ps1, sh);
        }
        if (t_ == 0) {
            sRsum[wc * 64 + qrow + g]     = ps0;
            sRsum[wc * 64 + qrow + g + 8] = ps1;
        }
        __syncthreads();            // (B) — also gates K-smem reuse for V
        l0 = l0 * corr0 + ps0 + sRsum[(1 - wc) * 64 + qrow + g];
        l1 = l1 * corr1 + ps1 + sRsum[(1 - wc) * 64 + qrow + g + 8];
        m0 = mn0; m1 = mn1;
        #pragma unroll
        for (int nf = 0; nf < 16; nf++) {
            o[nf][0] *= corr0; o[nf][1] *= corr0;
            o[nf][2] *= corr1; o[nf][3] *= corr1;
        }

        // pack P into bf16 hi/lo A-fragments (register reuse, no smem P)
        uint32_t ph[2][4], pl[2][4];
        #pragma unroll
        for (int kfp = 0; kfp < 2; kfp++) {
            int nA = 2 * kfp, nB = 2 * kfp + 1;
            float src[4][2] = {{sa[nA][0], sa[nA][1]}, {sa[nA][2], sa[nA][3]},
                               {sa[nB][0], sa[nB][1]}, {sa[nB][2], sa[nB][3]}};
            #pragma unroll
            for (int r = 0; r < 4; r++) {
                __nv_bfloat162 h2 = __floats2bfloat162_rn(src[r][0], src[r][1]);
                float lx = src[r][0] - __low2float(h2);
                float ly = src[r][1] - __high2float(h2);
                __nv_bfloat162 l2 = __floats2bfloat162_rn(lx, ly);
                ph[kfp][r] = *(uint32_t*)&h2;
                pl[kfp][r] = *(uint32_t*)&l2;
            }
        }

        // store V(kt) into KV smem
        #pragma unroll
        for (int u = 0; u < 4; u++) {
            *(uint4*)(sb + KH_OFF + lr[u] * KSTR + lc[u] * 8) = pref[u];
            *(uint4*)(sb + KL_OFF + lr[u] * KSTR + lc[u] * 8) = pref[4 + u];
        }
        __syncthreads();            // (C)

        // prefetch K(kt+1) — overlaps PV MMA
        if (kt + 1 < kt1) {
            const uint4* Kh4 = (const uint4*)(g_Kh + ((size_t)b * TT + (kt + 1) * 64) * DD);
            const uint4* Kl4 = (const uint4*)(g_Kl + ((size_t)b * TT + (kt + 1) * 64) * DD);
            #pragma unroll
            for (int u = 0; u < 4; u++) {
                pref[u]     = Kh4[lr[u] * 16 + lc[u]];
                pref[4 + u] = Kl4[lr[u] * 16 + lc[u]];
            }
        }

        // ---- O += P V : warp's 32 keys, full 128-d output ----
        #pragma unroll
        for (int kfp = 0; kfp < 2; kfp++) {
            #pragma unroll
            for (int nfp = 0; nfp < 8; nfp++) {
                uint32_t vh[4], vl[4];
                uint32_t av = sbase + (KH_OFF + (kb + kfp * 16 + lrow16) * KSTR + nfp * 16 + lhalf * 8) * 2;
                ldsm4t(vh, av);
                ldsm4t(vl, av + (KL_OFF - KH_OFF) * 2);
                // nfA = 2nfp: frag (r0,r1); nfB: (r2,r3)
                mma_bf16(o[2 * nfp], ph[kfp][0], ph[kfp][1], ph[kfp][2], ph[kfp][3], vh[0], vh[1]);
                mma_bf16(o[2 * nfp], ph[kfp][0], ph[kfp][1], ph[kfp][2], ph[kfp][3], vl[0], vl[1]);
                mma_bf16(o[2 * nfp], pl[kfp][0], pl[kfp][1], pl[kfp][2], pl[kfp][3], vh[0], vh[1]);
                mma_bf16(o[2 * nfp + 1], ph[kfp][0], ph[kfp][1], ph[kfp][2], ph[kfp][3], vh[2], vh[3]);
                mma_bf16(o[2 * nfp + 1], ph[kfp][0], ph[kfp][1], ph[kfp][2], ph[kfp][3], vl[2], vl[3]);
                mma_bf16(o[2 * nfp + 1], pl[kfp][0], pl[kfp][1], pl[kfp][2], pl[kfp][3], vh[2], vh[3]);
            }
        }
    }

    // ---- epilogue: combine the two key-half warps, write partials ----
    __syncthreads();
    float* sO = (float*)sb;          // reuse Q region (dead now); stride 132
    if (wc == 0) {
        #pragma unroll
        for (int nf = 0; nf < 16; nf++) {
            int col = 2 * t_ + 8 * nf;
            sO[(qrow + g) * 132 + col]     = o[nf][0];
            sO[(qrow + g) * 132 + col + 1] = o[nf][1];
            sO[(qrow + g + 8) * 132 + col]     = o[nf][2];
            sO[(qrow + g + 8) * 132 + col + 1] = o[nf][3];
        }
    }
    __syncthreads();
    if (wc == 1) {
        #pragma unroll
        for (int nf = 0; nf < 16; nf++) {
            int col = 2 * t_ + 8 * nf;
            float a0 = o[nf][0] + sO[(qrow + g) * 132 + col];
            float a1 = o[nf][1] + sO[(qrow + g) * 132 + col + 1];
            float a2 = o[nf][2] + sO[(qrow + g + 8) * 132 + col];
            float a3 = o[nf][3] + sO[(qrow + g + 8) * 132 + col + 1];
            *(float2*)&g_Opart[part_base + (size_t)(qrow + g) * DD + col]     = make_float2(a0, a1);
            *(float2*)&g_Opart[part_base + (size_t)(qrow + g + 8) * DD + col] = make_float2(a2, a3);
        }
        if (t_ == 0) {
            g_Mpart[ml_base + qrow + g]     = m0;
            g_Mpart[ml_base + qrow + g + 8] = m1;
            g_Lpart[ml_base + qrow + g]     = l0;
            g_Lpart[ml_base + qrow + g + 8] = l1;
        }
    }
}

// ---------------- merge the two splits ----------------
__global__ __launch_bounds__(128) void merge_kernel(float* __restrict__ Out) {
    int row = blockIdx.x;
    int d   = threadIdx.x;
    float m0 = g_Mpart[row];
    float m1 = g_Mpart[BB * TT + row];
    float l0 = g_Lpart[row];
    float l1 = g_Lpart[BB * TT + row];
    float m  = fmaxf(m0, m1);
    float a0 = __expf(m0 - m);
    float a1 = __expf(m1 - m);
    float inv = 1.0f / (a0 * l0 + a1 * l1);
    float o0 = g_Opart[(size_t)row * DD + d];
    float o1 = g_Opart[(size_t)(BB * TT + row) * DD + d];
    Out[(size_t)row * DD + d] = (a0 * o0 + a1 * o1) * inv;
}

// ---------------- launch ----------------
extern "C" void kernel_launch(void* const* d_in, const int* in_sizes, int n_in,
                              void* d_out, int out_size) {
    (void)in_sizes; (void)n_in; (void)out_size;
    const float* X  = (const float*)d_in[0];
    const float* Wq = (const float*)d_in[1];
    const float* Wk = (const float*)d_in[2];
    const float* Wv = (const float*)d_in[3];
    float* Out = (float*)d_out;

    rope_table_kernel<<<TT, DD / 2>>>();

    dim3 pg(BB * TT / 64, 3);
    proj_mma_kernel<<<pg, 256>>>(X, Wq, Wk, Wv);

    cudaFuncSetAttribute(attn_mma_kernel, cudaFuncAttributeMaxDynamicSharedMemorySize, ATTN_SMEM2);
    dim3 ag(2, TT / 64, BB);
    attn_mma_kernel<<<ag, 256, ATTN_SMEM2>>>();

    merge_kernel<<<BB * TT, 128>>>(Out);
}